// round 8
// baseline (speedup 1.0000x reference)
#include <cuda_runtime.h>

// Problem constants (shapes fixed by the dataset)
#define BB   64
#define KK   8
#define VV   128000
#define NS   25              // chunks per batch row
#define TPB  256
#define LCH  (VV / NS)       // 5120 floats per chunk
#define NW   (TPB / 32)      // 8 warps per block
#define SEG  128             // floats per segment (one warp-wide float4 iter)
#define SPW  5               // segments per warp (5*128 = 640 floats)
#define SEGS (NW * SPW)      // 40 segments per chunk
#define GRID 800             // each block handles chunks blk and blk+800
#define FULL 0xFFFFFFFFu

// Scratch (device globals — zero-initialized; g_done self-resets every call)
__device__ float g_ssum[BB * NS * SEGS];     // per-segment sums (256 KB)
__device__ float g_chunksum[BB * NS];
__device__ int   g_done[BB];

// ---------------------------------------------------------------------------
// Hierarchical CDF search for one batch, executed by one full warp.
// level 1: 25 chunk sums -> level 2: 40 segment sums -> level 3: 128 floats.
// ---------------------------------------------------------------------------
__device__ __forceinline__ void cdf_search(int b, int na, int allacc, int r,
                                           const float* __restrict__ dp,
                                           const float* __restrict__ op,
                                           const float* __restrict__ su,
                                           float* __restrict__ out, int lane)
{
    // level 1: 25 chunk sums
    float cs = (lane < NS) ? __ldcg(&g_chunksum[b * NS + lane]) : 0.0f;
    float x = cs;
#pragma unroll
    for (int o = 1; o < 32; o <<= 1) {
        float y = __shfl_up_sync(FULL, x, o);
        if (lane >= o) x += y;
    }
    float tot = __shfl_sync(FULL, x, NS - 1);
    float T = allacc ? su[b] : su[b] * tot;

    unsigned bal = __ballot_sync(FULL, (lane < NS) && (x >= T));
    int token;
    if (bal == 0) {
        token = VV - 1;
    } else {
        int sc = __ffs(bal) - 1;
        float base = __shfl_sync(FULL, x, sc) - __shfl_sync(FULL, cs, sc);

        // level 2: 40 segment sums in chunk sc
        const float* ss = &g_ssum[(b * NS + sc) * SEGS];
        int   j_found = -1;
        float base_t  = 0.0f;
        float running = base;
#pragma unroll
        for (int g = 0; g < 2; ++g) {
            int j = g * 32 + lane;
            float v = (j < SEGS) ? __ldcg(&ss[j]) : 0.0f;
            float xx = v;
#pragma unroll
            for (int o = 1; o < 32; o <<= 1) {
                float y = __shfl_up_sync(FULL, xx, o);
                if (lane >= o) xx += y;
            }
            unsigned bb2 = __ballot_sync(FULL, (j < SEGS) && (running + xx >= T));
            if (bb2) {
                int l = __ffs(bb2) - 1;
                j_found = g * 32 + l;
                base_t  = running + __shfl_sync(FULL, xx, l)
                                  - __shfl_sync(FULL, v, l);
                break;
            }
            running += __shfl_sync(FULL, xx, 31);
        }

        if (j_found < 0) {
            token = min(sc * LCH + LCH, VV - 1);         // ulp-tie fallback
        } else {
            // level 3: one 128-float segment, coalesced re-read
            int off0 = sc * LCH + j_found * SEG;
            int ob2  = (b * (KK + 1) + (allacc ? KK : r)) * VV + off0;
            int db2  = (b * KK + r) * VV + off0;
            float4 ov = ((const float4*)(op + ob2))[lane];
            float v0, v1, v2, v3;
            if (allacc) {
                v0 = ov.x; v1 = ov.y; v2 = ov.z; v3 = ov.w;
            } else {
                float4 dv = ((const float4*)(dp + db2))[lane];
                v0 = fmaxf(ov.x - dv.x, 0.f); v1 = fmaxf(ov.y - dv.y, 0.f);
                v2 = fmaxf(ov.z - dv.z, 0.f); v3 = fmaxf(ov.w - dv.w, 0.f);
            }
            float local = v0 + v1 + v2 + v3;
            float xx = local;
#pragma unroll
            for (int o = 1; o < 32; o <<= 1) {
                float y = __shfl_up_sync(FULL, xx, o);
                if (lane >= o) xx += y;
            }
            unsigned bb3 = __ballot_sync(FULL, base_t + xx >= T);
            if (!bb3) {
                token = min(off0 + SEG, VV - 1);          // ulp-tie fallback
            } else {
                int l = __ffs(bb3) - 1;
                float excl = base_t + __shfl_sync(FULL, xx, l)
                                    - __shfl_sync(FULL, local, l);
                float a0 = __shfl_sync(FULL, v0, l);
                float a1 = __shfl_sync(FULL, v1, l);
                float a2 = __shfl_sync(FULL, v2, l);
                float run = excl;
                int idx = 3;
                run += a0;
                if (run >= T) idx = 0;
                else { run += a1;
                    if (run >= T) idx = 1;
                    else { run += a2; if (run >= T) idx = 2; }
                }
                token = min(off0 + l * 4 + idx, VV - 1);
            }
        }
    }

    if (lane == 0)
        out[b * (KK + 1) + na] = (float)token;
}

// ---------------------------------------------------------------------------
// Fused kernel: each block handles the SAME chunk index s of two batches
// (bA and bA+32), giving every warp two independent coalesced load streams
// and halving the per-block acceptance-latency bubbles.
// ---------------------------------------------------------------------------
__global__ void __launch_bounds__(TPB, 4)
k_fused(const int*   __restrict__ dtok,
        const float* __restrict__ dp,
        const float* __restrict__ op,
        const float* __restrict__ unif,
        const float* __restrict__ su,
        float*       __restrict__ out)
{
    int blk = blockIdx.x;
    int t = threadIdx.x, lane = t & 31, wid = t >> 5;

    int cA = blk,        bA = cA / NS, sA = cA % NS;
    int cB = blk + GRID, bB = bA + 32;          // 800 = 32*25 -> sB == sA

    // ---- acceptance for BOTH batches in one warp-wide gather round ----
    bool acc = false;
    if (lane < 16) {
        int bb = (lane < 8) ? bA : bB;
        int k  = lane & 7;
        int tok  = dtok[bb * KK + k];
        float pd = dp[(bb * KK + k) * VV + tok];
        float po = op[(bb * (KK + 1) + k) * VV + tok];
        acc = unif[bb * KK + k] < fminf(1.0f, po / pd);
    }
    unsigned bits = __ballot_sync(FULL, acc);
    int naA = __ffs(~(bits & 0xFFu)) - 1;
    int naB = __ffs(~((bits >> 8) & 0xFFu)) - 1;
    int allaccA = (naA == KK), allaccB = (naB == KK);
    int rA = min(naA, KK - 1), rB = min(naB, KK - 1);

    // ---- two independent coalesced streams (4 indep float4 loads / iter) ----
    int row = sA * LCH + wid * (SPW * SEG);
    const float4* oA4 = (const float4*)(op + (bA * (KK + 1) + (allaccA ? KK : rA)) * VV + row);
    const float4* dA4 = (const float4*)(dp + (bA * KK + rA) * VV + row);
    const float4* oB4 = (const float4*)(op + (bB * (KK + 1) + (allaccB ? KK : rB)) * VV + row);
    const float4* dB4 = (const float4*)(dp + (bB * KK + rB) * VV + row);

    float pA[SPW], pB[SPW];
#pragma unroll
    for (int i = 0; i < SPW; ++i) {
        float4 a = oA4[i * 32 + lane];
        float4 e = dA4[i * 32 + lane];   // always a valid row (r = min(na,7))
        float4 c = oB4[i * 32 + lane];
        float4 f = dB4[i * 32 + lane];
        pA[i] = allaccA ? (a.x + a.y + a.z + a.w)
                        : (fmaxf(a.x - e.x, 0.f) + fmaxf(a.y - e.y, 0.f)
                         + fmaxf(a.z - e.z, 0.f) + fmaxf(a.w - e.w, 0.f));
        pB[i] = allaccB ? (c.x + c.y + c.z + c.w)
                        : (fmaxf(c.x - f.x, 0.f) + fmaxf(c.y - f.y, 0.f)
                         + fmaxf(c.z - f.z, 0.f) + fmaxf(c.w - f.w, 0.f));
    }

    // ---- segment sums (warp tree-reduce), shared + global ----
    __shared__ float ssh[2 * SEGS];
#pragma unroll
    for (int i = 0; i < SPW; ++i) {
        float w = pA[i];
#pragma unroll
        for (int o = 16; o > 0; o >>= 1) w += __shfl_down_sync(FULL, w, o);
        if (lane == 0) {
            ssh[wid * SPW + i] = w;
            g_ssum[cA * SEGS + wid * SPW + i] = w;
        }
        float w2 = pB[i];
#pragma unroll
        for (int o = 16; o > 0; o >>= 1) w2 += __shfl_down_sync(FULL, w2, o);
        if (lane == 0) {
            ssh[SEGS + wid * SPW + i] = w2;
            g_ssum[cB * SEGS + wid * SPW + i] = w2;
        }
    }

    // ---- token scaffolding (chunk s==0 writes both batches' slots) ----
    if (sA == 0) {
        if (t <= KK && t != naA)
            out[bA * (KK + 1) + t] = (t < naA) ? (float)dtok[bA * KK + t] : -1.0f;
        if (t == KK + 1)
            out[BB * (KK + 1) + bA] = (float)naA;
        int t2 = t - 64;
        if (t2 >= 0 && t2 <= KK && t2 != naB)
            out[bB * (KK + 1) + t2] = (t2 < naB) ? (float)dtok[bB * KK + t2] : -1.0f;
        if (t == 64 + KK + 1)
            out[BB * (KK + 1) + bB] = (float)naB;
    }

    __syncthreads();
    if (t == 0) {                      // sequential order == level-2 scan order
        float c = 0.0f;
#pragma unroll
        for (int j = 0; j < SEGS; ++j) c += ssh[j];
        g_chunksum[cA] = c;
    }
    if (t == 32) {
        float c = 0.0f;
#pragma unroll
        for (int j = 0; j < SEGS; ++j) c += ssh[SEGS + j];
        g_chunksum[cB] = c;
    }

    // ---- publish (all writers fence) + elect last block per batch ----
    __shared__ int shLast;
    __threadfence();                   // writers: lane0s (g_ssum), t0/t32 pending
    __syncthreads();
    if (t == 0) {
        __threadfence();               // order t0's own chunksum store
        int oA = atomicAdd(&g_done[bA], 1);
        int oB = atomicAdd(&g_done[bB], 1);
        int la = (oA == NS - 1) ? 1 : 0;
        int lb = (oB == NS - 1) ? 2 : 0;
        if (la) g_done[bA] = 0;        // self-reset for graph replay
        if (lb) g_done[bB] = 0;
        shLast = la | lb;
    }
    __syncthreads();
    int lf = shLast;
    if (wid == 0 && (lf & 1)) {
        __threadfence();               // acquire before cross-block reads
        cdf_search(bA, naA, allaccA, rA, dp, op, su, out, lane);
    }
    if (wid == 1 && (lf & 2)) {
        __threadfence();
        cdf_search(bB, naB, allaccB, rB, dp, op, su, out, lane);
    }
}

// ---------------------------------------------------------------------------
// Host launcher: classify inputs by element count (order-agnostic).
// ---------------------------------------------------------------------------
extern "C" void kernel_launch(void* const* d_in, const int* in_sizes, int n_in,
                              void* d_out, int out_size)
{
    const int*   dtok = nullptr;
    const float* dp   = nullptr;
    const float* op   = nullptr;
    const float* unif = nullptr;
    const float* su   = nullptr;

    int n512 = 0;
    for (int i = 0; i < n_in; ++i) {
        long sz = (long)in_sizes[i];
        if (sz == (long)BB * KK * VV)            dp = (const float*)d_in[i];
        else if (sz == (long)BB * (KK + 1) * VV) op = (const float*)d_in[i];
        else if (sz == BB)                       su = (const float*)d_in[i];
        else if (sz == BB * KK) {
            // relative order: draft_tokens, oracle_tokens, uniforms
            if      (n512 == 0) dtok = (const int*)d_in[i];
            else if (n512 == 2) unif = (const float*)d_in[i];
            ++n512;
        }
    }

    float* out = (float*)d_out;  // [tokens (B*(K+1)) | num_accepted (B)] as f32

    k_fused<<<GRID, TPB>>>(dtok, dp, op, unif, su, out);
}

// round 9
// speedup vs baseline: 1.0038x; 1.0038x over previous
#include <cuda_runtime.h>
#include <cstdint>

// Problem constants (shapes fixed by the dataset)
#define BB   64
#define KK   8
#define VV   128000
#define NS   25              // chunks per batch row
#define TPB  256
#define LCH  (VV / NS)       // 5120 floats per chunk
#define NW   (TPB / 32)      // 8 warps per block
#define SEG  128             // floats per segment
#define SPW  5               // segments per warp (5*128 = 640 floats)
#define SEGS (NW * SPW)      // 40 segments per chunk
#define CH_BYTES (LCH * 4)   // 20480 bytes per row-chunk (16B-aligned)
#define FULL 0xFFFFFFFFu

// Scratch (device globals — zero-initialized; g_done self-resets every call)
__device__ float g_ssum[BB * NS * SEGS];
__device__ float g_chunksum[BB * NS];
__device__ int   g_done[BB];

__device__ __forceinline__ uint32_t smem_u32(const void* p) {
    uint32_t a;
    asm("{ .reg .u64 t; cvta.to.shared.u64 t, %1; cvt.u32.u64 %0, t; }"
        : "=r"(a) : "l"(p));
    return a;
}

// ---------------------------------------------------------------------------
// Hierarchical CDF search for one batch (one warp).
// level 1: 25 chunk sums -> level 2: 40 segment sums -> level 3: 128 floats.
// ---------------------------------------------------------------------------
__device__ __forceinline__ void cdf_search(int b, int na, int allacc, int r,
                                           const float* __restrict__ dp,
                                           const float* __restrict__ op,
                                           const float* __restrict__ su,
                                           float* __restrict__ out, int lane)
{
    float cs = (lane < NS) ? __ldcg(&g_chunksum[b * NS + lane]) : 0.0f;
    float x = cs;
#pragma unroll
    for (int o = 1; o < 32; o <<= 1) {
        float y = __shfl_up_sync(FULL, x, o);
        if (lane >= o) x += y;
    }
    float tot = __shfl_sync(FULL, x, NS - 1);
    float T = allacc ? su[b] : su[b] * tot;

    unsigned bal = __ballot_sync(FULL, (lane < NS) && (x >= T));
    int token;
    if (bal == 0) {
        token = VV - 1;
    } else {
        int sc = __ffs(bal) - 1;
        float base = __shfl_sync(FULL, x, sc) - __shfl_sync(FULL, cs, sc);

        const float* ss = &g_ssum[(b * NS + sc) * SEGS];
        int   j_found = -1;
        float base_t  = 0.0f;
        float running = base;
#pragma unroll
        for (int g = 0; g < 2; ++g) {
            int j = g * 32 + lane;
            float v = (j < SEGS) ? __ldcg(&ss[j]) : 0.0f;
            float xx = v;
#pragma unroll
            for (int o = 1; o < 32; o <<= 1) {
                float y = __shfl_up_sync(FULL, xx, o);
                if (lane >= o) xx += y;
            }
            unsigned bb2 = __ballot_sync(FULL, (j < SEGS) && (running + xx >= T));
            if (bb2) {
                int l = __ffs(bb2) - 1;
                j_found = g * 32 + l;
                base_t  = running + __shfl_sync(FULL, xx, l)
                                  - __shfl_sync(FULL, v, l);
                break;
            }
            running += __shfl_sync(FULL, xx, 31);
        }

        if (j_found < 0) {
            token = min(sc * LCH + LCH, VV - 1);         // ulp-tie fallback
        } else {
            int off0 = sc * LCH + j_found * SEG;
            int ob2  = (b * (KK + 1) + (allacc ? KK : r)) * VV + off0;
            int db2  = (b * KK + r) * VV + off0;
            float4 ov = ((const float4*)(op + ob2))[lane];
            float v0, v1, v2, v3;
            if (allacc) {
                v0 = ov.x; v1 = ov.y; v2 = ov.z; v3 = ov.w;
            } else {
                float4 dv = ((const float4*)(dp + db2))[lane];
                v0 = fmaxf(ov.x - dv.x, 0.f); v1 = fmaxf(ov.y - dv.y, 0.f);
                v2 = fmaxf(ov.z - dv.z, 0.f); v3 = fmaxf(ov.w - dv.w, 0.f);
            }
            float local = v0 + v1 + v2 + v3;
            float xx = local;
#pragma unroll
            for (int o = 1; o < 32; o <<= 1) {
                float y = __shfl_up_sync(FULL, xx, o);
                if (lane >= o) xx += y;
            }
            unsigned bb3 = __ballot_sync(FULL, base_t + xx >= T);
            if (!bb3) {
                token = min(off0 + SEG, VV - 1);          // ulp-tie fallback
            } else {
                int l = __ffs(bb3) - 1;
                float excl = base_t + __shfl_sync(FULL, xx, l)
                                    - __shfl_sync(FULL, local, l);
                float a0 = __shfl_sync(FULL, v0, l);
                float a1 = __shfl_sync(FULL, v1, l);
                float a2 = __shfl_sync(FULL, v2, l);
                float run = excl;
                int idx = 3;
                run += a0;
                if (run >= T) idx = 0;
                else { run += a1;
                    if (run >= T) idx = 1;
                    else { run += a2; if (run >= T) idx = 2; }
                }
                token = min(off0 + l * 4 + idx, VV - 1);
            }
        }
    }

    if (lane == 0)
        out[b * (KK + 1) + na] = (float)token;
}

// ---------------------------------------------------------------------------
// Fused kernel: TMA-staged streaming. One chunk per block (grid = 1600).
// cp.async.bulk pulls the 20KB oracle + 20KB draft row-chunks into smem with
// zero register pressure; 5 resident blocks/SM keep ~200KB in flight per SM.
// ---------------------------------------------------------------------------
__global__ void __launch_bounds__(TPB)
k_fused(const int*   __restrict__ dtok,
        const float* __restrict__ dp,
        const float* __restrict__ op,
        const float* __restrict__ unif,
        const float* __restrict__ su,
        float*       __restrict__ out)
{
    __shared__ alignas(16) float sh_o[LCH];
    __shared__ alignas(16) float sh_d[LCH];
    __shared__ alignas(8)  unsigned long long mbar;
    __shared__ float ssh[SEGS];
    __shared__ int   sh_na;

    int blk = blockIdx.x;
    int b = blk / NS, s = blk % NS;
    int t = threadIdx.x, lane = t & 31, wid = t >> 5;

    // ---- acceptance (warp 0) + mbarrier init ----
    if (wid == 0) {
        bool acc = false;
        if (lane < KK) {
            int tok  = dtok[b * KK + lane];
            float pd = dp[(b * KK + lane) * VV + tok];
            float po = op[(b * (KK + 1) + lane) * VV + tok];
            acc = unif[b * KK + lane] < fminf(1.0f, po / pd);
        }
        unsigned bits = __ballot_sync(FULL, acc) & ((1u << KK) - 1u);
        int na0 = __ffs(~bits) - 1;
        if (lane == 0) {
            sh_na = na0;
            asm volatile("mbarrier.init.shared.b64 [%0], %1;"
                         :: "r"(smem_u32(&mbar)), "r"(1) : "memory");
        }
    }
    __syncthreads();
    int na     = sh_na;
    int allacc = (na == KK);
    int r      = min(na, KK - 1);

    // ---- issue TMA bulk copies (t0 only; zero register-file cost) ----
    if (t == 0) {
        const float* orow = op + (b * (KK + 1) + (allacc ? KK : r)) * VV + s * LCH;
        const float* drow = dp + (b * KK + r) * VV + s * LCH;
        uint32_t mb    = smem_u32(&mbar);
        uint32_t bytes = allacc ? CH_BYTES : 2 * CH_BYTES;
        asm volatile("mbarrier.arrive.expect_tx.shared.b64 _, [%0], %1;"
                     :: "r"(mb), "r"(bytes) : "memory");
        asm volatile(
            "cp.async.bulk.shared::cluster.global.mbarrier::complete_tx::bytes "
            "[%0], [%1], %2, [%3];"
            :: "r"(smem_u32(sh_o)), "l"(orow), "r"((uint32_t)CH_BYTES), "r"(mb)
            : "memory");
        if (!allacc)
            asm volatile(
                "cp.async.bulk.shared::cluster.global.mbarrier::complete_tx::bytes "
                "[%0], [%1], %2, [%3];"
                :: "r"(smem_u32(sh_d)), "l"(drow), "r"((uint32_t)CH_BYTES), "r"(mb)
                : "memory");
    }

    // ---- token scaffolding overlapped with TMA (chunk s==0 only) ----
    if (s == 0) {
        if (t <= KK && t != na)
            out[b * (KK + 1) + t] = (t < na) ? (float)dtok[b * KK + t] : -1.0f;
        if (t == KK + 1)
            out[BB * (KK + 1) + b] = (float)na;
    }

    // ---- wait for TMA completion (parity 0; barrier fresh per launch) ----
    {
        uint32_t mb = smem_u32(&mbar);
        uint32_t done;
        asm volatile(
            "{\n\t.reg .pred p;\n\t"
            "mbarrier.try_wait.parity.acquire.cta.shared::cta.b64 p, [%1], 0;\n\t"
            "selp.b32 %0, 1, 0, p;\n\t}"
            : "=r"(done) : "r"(mb) : "memory");
        if (!done) {
            asm volatile(
                "{\n\t.reg .pred P1;\n\t"
                "W%=:\n\t"
                "mbarrier.try_wait.parity.acquire.cta.shared::cta.b64 P1, [%0], 0, 0x989680;\n\t"
                "@P1 bra D%=;\n\t"
                "bra W%=;\n\t"
                "D%=:\n\t}"
                :: "r"(mb) : "memory");
        }
    }

    // ---- compute from smem: conflict-free LDS.128, 5 segments per warp ----
    const float4* o4 = (const float4*)sh_o;
    const float4* d4 = (const float4*)sh_d;
#pragma unroll
    for (int i = 0; i < SPW; ++i) {
        int idx = wid * (SPW * 32) + i * 32 + lane;
        float4 a = o4[idx];
        float p;
        if (allacc) {
            p = a.x + a.y + a.z + a.w;
        } else {
            float4 e = d4[idx];
            p = fmaxf(a.x - e.x, 0.f) + fmaxf(a.y - e.y, 0.f)
              + fmaxf(a.z - e.z, 0.f) + fmaxf(a.w - e.w, 0.f);
        }
        float w = p;
#pragma unroll
        for (int o = 16; o > 0; o >>= 1)
            w += __shfl_down_sync(FULL, w, o);
        if (lane == 0) {
            ssh[wid * SPW + i] = w;
            g_ssum[blk * SEGS + wid * SPW + i] = w;
        }
    }

    __syncthreads();
    if (t == 0) {                     // sequential order == level-2 scan order
        float c = 0.0f;
#pragma unroll
        for (int j = 0; j < SEGS; ++j) c += ssh[j];
        g_chunksum[blk] = c;
    }

    // ---- publish + elect last block of this batch ----
    __shared__ int sh_last;
    __syncthreads();
    if (t == 0) {
        __threadfence();              // make g_ssum/g_chunksum device-visible
        int old = atomicAdd(&g_done[b], 1);
        sh_last = (old == NS - 1);
        if (sh_last) g_done[b] = 0;   // self-reset for graph replay
    }
    __syncthreads();
    if (!sh_last || wid != 0) return;

    __threadfence();                  // acquire before cross-block reads
    cdf_search(b, na, allacc, r, dp, op, su, out, lane);
}

// ---------------------------------------------------------------------------
// Host launcher: classify inputs by element count (order-agnostic).
// ---------------------------------------------------------------------------
extern "C" void kernel_launch(void* const* d_in, const int* in_sizes, int n_in,
                              void* d_out, int out_size)
{
    const int*   dtok = nullptr;
    const float* dp   = nullptr;
    const float* op   = nullptr;
    const float* unif = nullptr;
    const float* su   = nullptr;

    int n512 = 0;
    for (int i = 0; i < n_in; ++i) {
        long sz = (long)in_sizes[i];
        if (sz == (long)BB * KK * VV)            dp = (const float*)d_in[i];
        else if (sz == (long)BB * (KK + 1) * VV) op = (const float*)d_in[i];
        else if (sz == BB)                       su = (const float*)d_in[i];
        else if (sz == BB * KK) {
            // relative order: draft_tokens, oracle_tokens, uniforms
            if      (n512 == 0) dtok = (const int*)d_in[i];
            else if (n512 == 2) unif = (const float*)d_in[i];
            ++n512;
        }
    }

    float* out = (float*)d_out;  // [tokens (B*(K+1)) | num_accepted (B)] as f32

    k_fused<<<BB * NS, TPB>>>(dtok, dp, op, unif, su, out);
}